// round 1
// baseline (speedup 1.0000x reference)
#include <cuda_runtime.h>
#include <cstdint>

// Problem constants
#define BLD   1024        // B*L tokens
#define DIM   768
#define LSEQ  512
#define NBATCH 2
#define NSTATE 16
#define NVOC  50257

// ---------------- scratch (device globals; no allocation allowed) ----------
__device__ float g_x [BLD*DIM];
__device__ float g_xn[BLD*DIM];
__device__ float g_xr[BLD*2*DIM];
__device__ float g_xc[BLD*DIM];
__device__ float g_dt[BLD*DIM];
__device__ float g_y [BLD*DIM];

// ---------------- packed f32x2 FMA (Blackwell fast fp32 path) --------------
__device__ __forceinline__ unsigned long long fma2(unsigned long long a,
                                                   unsigned long long b,
                                                   unsigned long long c) {
    unsigned long long d;
    asm("fma.rn.f32x2 %0, %1, %2, %3;" : "=l"(d) : "l"(a), "l"(b), "l"(c));
    return d;
}

__device__ __forceinline__ float fast_sigmoid(float z) {
    return 1.0f / (1.0f + __expf(-z));
}

// ---------------- embedding gather -----------------------------------------
__global__ void embed_kernel(const int* __restrict__ tokens,
                             const float* __restrict__ emb) {
    int row = blockIdx.x;                      // 0..1023
    int tok = tokens[row];
    const float4* src = (const float4*)(emb + (size_t)tok * DIM);
    float4* dst = (float4*)(g_x + (size_t)row * DIM);
    dst[threadIdx.x] = src[threadIdx.x];       // 192 threads * float4 = 768
}

// ---------------- layernorm -------------------------------------------------
__global__ void ln_kernel(const float* __restrict__ x,
                          const float* __restrict__ g,
                          const float* __restrict__ b,
                          float* __restrict__ out) {
    int row = blockIdx.x;
    const float* xp = x + (size_t)row * DIM;
    float s = 0.f, s2 = 0.f;
    for (int i = threadIdx.x; i < DIM; i += 256) {
        float v = xp[i];
        s += v; s2 += v * v;
    }
#pragma unroll
    for (int o = 16; o; o >>= 1) {
        s  += __shfl_xor_sync(0xffffffffu, s,  o);
        s2 += __shfl_xor_sync(0xffffffffu, s2, o);
    }
    __shared__ float sh[16];
    int w = threadIdx.x >> 5, lane = threadIdx.x & 31;
    if (lane == 0) { sh[w] = s; sh[8 + w] = s2; }
    __syncthreads();
    s = 0.f; s2 = 0.f;
#pragma unroll
    for (int i = 0; i < 8; i++) { s += sh[i]; s2 += sh[8 + i]; }
    float m   = s * (1.0f / DIM);
    float var = s2 * (1.0f / DIM) - m * m;
    float inv = rsqrtf(var + 1e-5f);
    float* op = out + (size_t)row * DIM;
    for (int i = threadIdx.x; i < DIM; i += 256)
        op[i] = (xp[i] - m) * inv * g[i] + b[i];
}

// ---------------- depthwise conv(width 3) + silu ----------------------------
__global__ void conv_silu_kernel(const float* __restrict__ cw,   // [D,3]
                                 const float* __restrict__ cb) { // [D]
    int idx = blockIdx.x * blockDim.x + threadIdx.x;             // B*L*D
    if (idx >= BLD * DIM) return;
    int d = idx % DIM;
    int l = (idx / DIM) % LSEQ;
    int b = idx / (DIM * LSEQ);
    const float* base = g_xr + (size_t)b * LSEQ * (2 * DIM);     // xi = xr[...,:D]
    float xm = (l > 0)        ? base[(size_t)(l - 1) * 2 * DIM + d] : 0.f;
    float x0 =                  base[(size_t)l       * 2 * DIM + d];
    float xp = (l < LSEQ - 1) ? base[(size_t)(l + 1) * 2 * DIM + d] : 0.f;
    float z = xm * cw[d * 3 + 0] + x0 * cw[d * 3 + 1] + xp * cw[d * 3 + 2] + cb[d];
    g_xc[idx] = z * fast_sigmoid(z);
}

// ---------------- selective scan (thread per (b,d,s)) ------------------------
__global__ void scan_kernel(const float* __restrict__ A_log,   // [D,S]
                            const float* __restrict__ Dp) {    // [D]
    int tid = blockIdx.x * blockDim.x + threadIdx.x;           // 24576
    int s = tid & (NSTATE - 1);
    int d = (tid >> 4) % DIM;
    int b = tid / (DIM * NSTATE);
    float A  = -__expf(A_log[d * NSTATE + s]);
    float Dd = Dp[d];
    const float* dtp  = g_dt + (size_t)b * LSEQ * DIM + d;
    const float* xcp  = g_xc + (size_t)b * LSEQ * DIM + d;
    const float* resp = g_xr + (size_t)b * LSEQ * (2 * DIM) + DIM + d;
    float* yp = g_y + (size_t)b * LSEQ * DIM + d;
    float h = 0.f;
    for (int l = 0; l < LSEQ; l++) {
        float dtv = dtp[(size_t)l * DIM];
        float xv  = xcp[(size_t)l * DIM];
        h = h * __expf(A * dtv) + xv;
        float sum = h;
        sum += __shfl_xor_sync(0xffffffffu, sum, 1);
        sum += __shfl_xor_sync(0xffffffffu, sum, 2);
        sum += __shfl_xor_sync(0xffffffffu, sum, 4);
        sum += __shfl_xor_sync(0xffffffffu, sum, 8);
        if (s == 0) {
            float r = resp[(size_t)l * 2 * DIM];
            yp[(size_t)l * DIM] = sum * Dd * (r * fast_sigmoid(r));
        }
    }
}

// ---------------- SGEMM: C[M,N] = epilogue(A[M,K] * B[N,K]^T) ---------------
// 128x128 tile, BK=8, 256 threads, 8x8 per thread via packed f32x2 FMA.
// MODE 0: store   MODE 1: sigmoid(acc + bias[n])   MODE 2: C += acc (residual)
template <int MODE>
__global__ void __launch_bounds__(256, 2)
sgemm_tn(const float* __restrict__ A, const float* __restrict__ B,
         const float* __restrict__ bias, float* __restrict__ C,
         int M, int N, int K) {
    __shared__ __align__(16) float2 As2[8][128];  // duplicated (a,a) pairs
    __shared__ __align__(16) float  Bs [8][128];

    int bm = blockIdx.y * 128;
    int bn = blockIdx.x * 128;
    int t  = threadIdx.x;
    int lrow = t >> 1;
    int lk   = (t & 1) * 4;
    int ty4  = (t >> 4) * 4;
    int tx4  = (t & 15) * 4;

    const float* Aptr = A + (size_t)(bm + lrow) * K + lk;
    const float* Bptr = B + (size_t)(bn + lrow) * K + lk;
    bool bvalid = (bn + lrow) < N;

    unsigned long long acc2[8][4];
#pragma unroll
    for (int i = 0; i < 8; i++)
#pragma unroll
        for (int j = 0; j < 4; j++) acc2[i][j] = 0ull;

    for (int k0 = 0; k0 < K; k0 += 8) {
        float4 av = *(const float4*)(Aptr + k0);
        float4 bv = bvalid ? *(const float4*)(Bptr + k0) : make_float4(0.f, 0.f, 0.f, 0.f);
        As2[lk + 0][lrow] = make_float2(av.x, av.x);
        As2[lk + 1][lrow] = make_float2(av.y, av.y);
        As2[lk + 2][lrow] = make_float2(av.z, av.z);
        As2[lk + 3][lrow] = make_float2(av.w, av.w);
        Bs [lk + 0][lrow] = bv.x;
        Bs [lk + 1][lrow] = bv.y;
        Bs [lk + 2][lrow] = bv.z;
        Bs [lk + 3][lrow] = bv.w;
        __syncthreads();
#pragma unroll
        for (int kk = 0; kk < 8; kk++) {
            ulonglong2 a01 = *(const ulonglong2*)&As2[kk][ty4];
            ulonglong2 a23 = *(const ulonglong2*)&As2[kk][ty4 + 2];
            ulonglong2 a45 = *(const ulonglong2*)&As2[kk][ty4 + 64];
            ulonglong2 a67 = *(const ulonglong2*)&As2[kk][ty4 + 66];
            ulonglong2 b03 = *(const ulonglong2*)&Bs[kk][tx4];
            ulonglong2 b47 = *(const ulonglong2*)&Bs[kk][tx4 + 64];
            unsigned long long a[8] = {a01.x, a01.y, a23.x, a23.y,
                                       a45.x, a45.y, a67.x, a67.y};
            unsigned long long bb[4] = {b03.x, b03.y, b47.x, b47.y};
#pragma unroll
            for (int i = 0; i < 8; i++)
#pragma unroll
                for (int j = 0; j < 4; j++)
                    acc2[i][j] = fma2(a[i], bb[j], acc2[i][j]);
        }
        __syncthreads();
    }

    // epilogue
#pragma unroll
    for (int i = 0; i < 8; i++) {
        int m = bm + ((i < 4) ? (ty4 + i) : (64 + ty4 + i - 4));
        float* crow = C + (size_t)m * N;
#pragma unroll
        for (int j2 = 0; j2 < 4; j2++) {
            float lo = __uint_as_float((unsigned)(acc2[i][j2] & 0xffffffffull));
            float hi = __uint_as_float((unsigned)(acc2[i][j2] >> 32));
            int jbase = (j2 < 2) ? (tx4 + j2 * 2) : (64 + tx4 + (j2 - 2) * 2);
            int n0 = bn + jbase;
            int n1 = n0 + 1;
            if (MODE == 0) {
                if (n0 < N) crow[n0] = lo;
                if (n1 < N) crow[n1] = hi;
            } else if (MODE == 1) {
                if (n0 < N) crow[n0] = fast_sigmoid(lo + bias[n0]);
                if (n1 < N) crow[n1] = fast_sigmoid(hi + bias[n1]);
            } else {
                if (n0 < N) crow[n0] += lo;
                if (n1 < N) crow[n1] += hi;
            }
        }
    }
}

// ---------------- driver -----------------------------------------------------
extern "C" void kernel_launch(void* const* d_in, const int* in_sizes, int n_in,
                              void* d_out, int out_size) {
    const int*   tokens = (const int*)  d_in[0];
    const float* emb    = (const float*)d_in[1];
    const float* ln_g   = (const float*)d_in[2];
    const float* ln_b   = (const float*)d_in[3];
    const float* in_w   = (const float*)d_in[4];
    const float* conv_w = (const float*)d_in[5];
    const float* conv_b = (const float*)d_in[6];
    const float* dt_w   = (const float*)d_in[7];
    const float* dt_b   = (const float*)d_in[8];
    const float* A_log  = (const float*)d_in[9];
    const float* D_par  = (const float*)d_in[10];
    const float* out_w  = (const float*)d_in[11];
    const float* lnf_g  = (const float*)d_in[12];
    const float* lnf_b  = (const float*)d_in[13];
    const float* head_w = (const float*)d_in[14];
    float* out = (float*)d_out;

    float *x, *xn, *xr, *xc, *dt, *y;
    cudaGetSymbolAddress((void**)&x,  g_x);
    cudaGetSymbolAddress((void**)&xn, g_xn);
    cudaGetSymbolAddress((void**)&xr, g_xr);
    cudaGetSymbolAddress((void**)&xc, g_xc);
    cudaGetSymbolAddress((void**)&dt, g_dt);
    cudaGetSymbolAddress((void**)&y,  g_y);

    embed_kernel<<<BLD, 192>>>(tokens, emb);

    for (int l = 0; l < 4; l++) {
        ln_kernel<<<BLD, 256>>>(x, ln_g + l * DIM, ln_b + l * DIM, xn);
        // xr = xn @ in_w^T  (1024 x 1536)
        sgemm_tn<0><<<dim3(12, 8), 256>>>(xn, in_w + (size_t)l * 2 * DIM * DIM,
                                          nullptr, xr, BLD, 2 * DIM, DIM);
        conv_silu_kernel<<<(BLD * DIM + 255) / 256, 256>>>(conv_w + l * DIM * 3,
                                                           conv_b + l * DIM);
        // dt = sigmoid(xc @ dt_w^T + dt_b)  (1024 x 768)
        sgemm_tn<1><<<dim3(6, 8), 256>>>(xc, dt_w + (size_t)l * DIM * DIM,
                                         dt_b + l * DIM, dt, BLD, DIM, DIM);
        scan_kernel<<<96, 256>>>(A_log + l * DIM * NSTATE, D_par + l * DIM);
        // x += y @ out_w^T
        sgemm_tn<2><<<dim3(6, 8), 256>>>(y, out_w + (size_t)l * DIM * DIM,
                                         nullptr, x, BLD, DIM, DIM);
    }

    ln_kernel<<<BLD, 256>>>(x, lnf_g, lnf_b, xn);
    // logits = xn @ head_w^T  (1024 x 50257)
    sgemm_tn<0><<<dim3((NVOC + 127) / 128, 8), 256>>>(xn, head_w, nullptr, out,
                                                      BLD, NVOC, DIM);
    (void)in_sizes; (void)n_in; (void)out_size;
}

// round 2
// speedup vs baseline: 1.7938x; 1.7938x over previous
#include <cuda_runtime.h>
#include <cuda_bf16.h>
#include <cstdint>

// Problem constants
#define BLD   1024        // B*L tokens
#define DIM   768
#define LSEQ  512
#define NSTATE 16
#define NVOC  50257

// ---------------- scratch (device globals; no allocation allowed) ----------
__device__ float g_x [BLD*DIM];
__device__ float g_xn[BLD*DIM];
__device__ float g_xr[BLD*2*DIM];
__device__ float g_xc[BLD*DIM];
__device__ float g_dt[BLD*DIM];
__device__ float g_y [BLD*DIM];

__device__ __forceinline__ float fast_sigmoid(float z) {
    return 1.0f / (1.0f + __expf(-z));
}

// ---------------- embedding gather -----------------------------------------
__global__ void embed_kernel(const int* __restrict__ tokens,
                             const float* __restrict__ emb) {
    int row = blockIdx.x;                      // 0..1023
    int tok = tokens[row];
    const float4* src = (const float4*)(emb + (size_t)tok * DIM);
    float4* dst = (float4*)(g_x + (size_t)row * DIM);
    dst[threadIdx.x] = src[threadIdx.x];       // 192 threads * float4 = 768
}

// ---------------- layernorm -------------------------------------------------
__global__ void ln_kernel(const float* __restrict__ x,
                          const float* __restrict__ g,
                          const float* __restrict__ b,
                          float* __restrict__ out) {
    int row = blockIdx.x;
    const float* xp = x + (size_t)row * DIM;
    float s = 0.f, s2 = 0.f;
    for (int i = threadIdx.x; i < DIM; i += 256) {
        float v = xp[i];
        s += v; s2 += v * v;
    }
#pragma unroll
    for (int o = 16; o; o >>= 1) {
        s  += __shfl_xor_sync(0xffffffffu, s,  o);
        s2 += __shfl_xor_sync(0xffffffffu, s2, o);
    }
    __shared__ float sh[16];
    int w = threadIdx.x >> 5, lane = threadIdx.x & 31;
    if (lane == 0) { sh[w] = s; sh[8 + w] = s2; }
    __syncthreads();
    s = 0.f; s2 = 0.f;
#pragma unroll
    for (int i = 0; i < 8; i++) { s += sh[i]; s2 += sh[8 + i]; }
    float m   = s * (1.0f / DIM);
    float var = s2 * (1.0f / DIM) - m * m;
    float inv = rsqrtf(var + 1e-5f);
    float* op = out + (size_t)row * DIM;
    for (int i = threadIdx.x; i < DIM; i += 256)
        op[i] = (xp[i] - m) * inv * g[i] + b[i];
}

// ---------------- depthwise conv(width 3) + silu ----------------------------
__global__ void conv_silu_kernel(const float* __restrict__ cw,   // [D,3]
                                 const float* __restrict__ cb) { // [D]
    int idx = blockIdx.x * blockDim.x + threadIdx.x;             // B*L*D
    if (idx >= BLD * DIM) return;
    int d = idx % DIM;
    int l = (idx / DIM) % LSEQ;
    int b = idx / (DIM * LSEQ);
    const float* base = g_xr + (size_t)b * LSEQ * (2 * DIM);     // xi = xr[...,:D]
    float xm = (l > 0)        ? base[(size_t)(l - 1) * 2 * DIM + d] : 0.f;
    float x0 =                  base[(size_t)l       * 2 * DIM + d];
    float xp = (l < LSEQ - 1) ? base[(size_t)(l + 1) * 2 * DIM + d] : 0.f;
    float z = xm * cw[d * 3 + 0] + x0 * cw[d * 3 + 1] + xp * cw[d * 3 + 2] + cb[d];
    g_xc[idx] = z * fast_sigmoid(z);
}

// ---------------- selective scan (thread per (b,d,s)) ------------------------
__global__ void scan_kernel(const float* __restrict__ A_log,   // [D,S]
                            const float* __restrict__ Dp) {    // [D]
    int tid = blockIdx.x * blockDim.x + threadIdx.x;           // 24576
    int s = tid & (NSTATE - 1);
    int d = (tid >> 4) % DIM;
    int b = tid / (DIM * NSTATE);
    float A  = -__expf(A_log[d * NSTATE + s]);
    float Dd = Dp[d];
    const float* dtp  = g_dt + (size_t)b * LSEQ * DIM + d;
    const float* xcp  = g_xc + (size_t)b * LSEQ * DIM + d;
    const float* resp = g_xr + (size_t)b * LSEQ * (2 * DIM) + DIM + d;
    float* yp = g_y + (size_t)b * LSEQ * DIM + d;
    float h = 0.f;
    for (int l = 0; l < LSEQ; l++) {
        float dtv = dtp[(size_t)l * DIM];
        float xv  = xcp[(size_t)l * DIM];
        h = h * __expf(A * dtv) + xv;
        float sum = h;
        sum += __shfl_xor_sync(0xffffffffu, sum, 1);
        sum += __shfl_xor_sync(0xffffffffu, sum, 2);
        sum += __shfl_xor_sync(0xffffffffu, sum, 4);
        sum += __shfl_xor_sync(0xffffffffu, sum, 8);
        if (s == 0) {
            float r = resp[(size_t)l * 2 * DIM];
            yp[(size_t)l * DIM] = sum * Dd * (r * fast_sigmoid(r));
        }
    }
}

// ================= tensor-core GEMM (split-bf16, fp32-accurate) =============
// C[M,N] = epilogue(A[M,K] * B[N,K]^T), M = 1024 fixed (grid.x*128).
// 128x128 block tile, k-step 32, 8 warps, warp tile 32x64.
// Split: a = ah + al (bf16 each). acc = Ah*Bh + Ah*Bl + Al*Bh.
// MODE 0: store   MODE 1: sigmoid(acc + bias[n])   MODE 2: C += acc

__device__ __forceinline__ void ldsm4(unsigned r[4], unsigned addr) {
    asm volatile("ldmatrix.sync.aligned.m8n8.x4.shared.b16 {%0,%1,%2,%3}, [%4];"
                 : "=r"(r[0]), "=r"(r[1]), "=r"(r[2]), "=r"(r[3]) : "r"(addr));
}

__device__ __forceinline__ void mma16816(float c[4], const unsigned a[4],
                                         const unsigned b[2]) {
    asm volatile(
        "mma.sync.aligned.m16n8k16.row.col.f32.bf16.bf16.f32 "
        "{%0,%1,%2,%3}, {%4,%5,%6,%7}, {%8,%9}, {%0,%1,%2,%3};"
        : "+f"(c[0]), "+f"(c[1]), "+f"(c[2]), "+f"(c[3])
        : "r"(a[0]), "r"(a[1]), "r"(a[2]), "r"(a[3]), "r"(b[0]), "r"(b[1]));
}

__device__ __forceinline__ void cvt_pair(float x, float y,
                                         unsigned& h, unsigned& l) {
    __nv_bfloat162 hh = __floats2bfloat162_rn(x, y);
    float hx = __bfloat162float(hh.x);
    float hy = __bfloat162float(hh.y);
    __nv_bfloat162 ll = __floats2bfloat162_rn(x - hx, y - hy);
    h = *(unsigned*)&hh;
    l = *(unsigned*)&ll;
}

// smem stage layout (bytes): Ah @0, Al @10240, Bh @20480, Bl @30720
// each matrix: 128 rows x stride 40 bf16 (80B) -> 10240B. Stage = 40960B.
#define STAGE_BYTES 40960
#define GEMM_SMEM   (2 * STAGE_BYTES)

template <int MODE>
__global__ void __launch_bounds__(256)
gemm_mma(const float* __restrict__ A, const float* __restrict__ B,
         const float* __restrict__ bias, float* __restrict__ C,
         int N, int K) {
    extern __shared__ char smc[];
    int tid = threadIdx.x, lane = tid & 31, warp = tid >> 5;
    int wm = warp & 3, wn = warp >> 2;
    int bm = blockIdx.x * 128, bn = blockIdx.y * 128;
    unsigned sbase = (unsigned)__cvta_generic_to_shared(smc);

    // per-lane ldmatrix byte offsets within a stage
    unsigned aoff[2][2];
#pragma unroll
    for (int m = 0; m < 2; m++)
#pragma unroll
        for (int ks = 0; ks < 2; ks++) {
            int row = wm * 32 + m * 16 + (lane & 7) + ((lane & 8) ? 8 : 0);
            int col = ks * 16 + ((lane & 16) ? 8 : 0);
            aoff[m][ks] = (unsigned)(row * 40 + col) * 2;
        }
    unsigned boff[8];
#pragma unroll
    for (int n = 0; n < 8; n++) {
        int nrow = wn * 64 + n * 8 + (lane & 7);
        int kc = (lane >> 3) * 8;
        boff[n] = 20480u + (unsigned)(nrow * 40 + kc) * 2;
    }

    // global loader mapping: thread t handles rows (t>>3)+32j, k-cols (t&7)*4..+3
    int lr = tid >> 3;
    int lc = (tid & 7) * 4;
    const float* Ag = A + (size_t)(bm + lr) * K + lc;
    const float* Bg = B + (size_t)(bn + lr) * K + lc;
    bool bval[4];
#pragma unroll
    for (int j = 0; j < 4; j++) bval[j] = (bn + lr + 32 * j) < N;

    float4 ra[4], rb[4];

    float acc[2][8][4];
#pragma unroll
    for (int m = 0; m < 2; m++)
#pragma unroll
        for (int n = 0; n < 8; n++)
#pragma unroll
            for (int q = 0; q < 4; q++) acc[m][n][q] = 0.f;

    // preload tile 0
#pragma unroll
    for (int j = 0; j < 4; j++) {
        ra[j] = *(const float4*)(Ag + (size_t)(32 * j) * K);
        rb[j] = bval[j] ? *(const float4*)(Bg + (size_t)(32 * j) * K)
                        : make_float4(0.f, 0.f, 0.f, 0.f);
    }
    // store stage 0
    {
        char* base = smc;
#pragma unroll
        for (int j = 0; j < 4; j++) {
            unsigned off = (unsigned)((lr + 32 * j) * 40 + lc) * 2;
            unsigned h0, l0, h1, l1;
            cvt_pair(ra[j].x, ra[j].y, h0, l0);
            cvt_pair(ra[j].z, ra[j].w, h1, l1);
            *(uint2*)(base + off)          = make_uint2(h0, h1);
            *(uint2*)(base + off + 10240)  = make_uint2(l0, l1);
            cvt_pair(rb[j].x, rb[j].y, h0, l0);
            cvt_pair(rb[j].z, rb[j].w, h1, l1);
            *(uint2*)(base + off + 20480)  = make_uint2(h0, h1);
            *(uint2*)(base + off + 30720)  = make_uint2(l0, l1);
        }
    }
    __syncthreads();

    int T = K / 32;
    for (int i = 0; i < T; i++) {
        // prefetch next tile into registers
        if (i + 1 < T) {
            int k0 = (i + 1) * 32;
#pragma unroll
            for (int j = 0; j < 4; j++) {
                ra[j] = *(const float4*)(Ag + (size_t)(32 * j) * K + k0);
                rb[j] = bval[j] ? *(const float4*)(Bg + (size_t)(32 * j) * K + k0)
                                : make_float4(0.f, 0.f, 0.f, 0.f);
            }
        }
        unsigned st = sbase + (unsigned)(i & 1) * STAGE_BYTES;

        unsigned Ah[2][2][4], Al[2][2][4];
#pragma unroll
        for (int m = 0; m < 2; m++)
#pragma unroll
            for (int ks = 0; ks < 2; ks++) {
                ldsm4(Ah[m][ks], st + aoff[m][ks]);
                ldsm4(Al[m][ks], st + aoff[m][ks] + 10240u);
            }
#pragma unroll
        for (int n = 0; n < 8; n++) {
            unsigned bh[4], bl[4];
            ldsm4(bh, st + boff[n]);
            ldsm4(bl, st + boff[n] + 10240u);
#pragma unroll
            for (int ks = 0; ks < 2; ks++)
#pragma unroll
                for (int m = 0; m < 2; m++) {
                    mma16816(acc[m][n], Ah[m][ks], bh + ks * 2);
                    mma16816(acc[m][n], Ah[m][ks], bl + ks * 2);
                    mma16816(acc[m][n], Al[m][ks], bh + ks * 2);
                }
        }
        // stage next tile
        if (i + 1 < T) {
            char* base = smc + ((i + 1) & 1) * STAGE_BYTES;
#pragma unroll
            for (int j = 0; j < 4; j++) {
                unsigned off = (unsigned)((lr + 32 * j) * 40 + lc) * 2;
                unsigned h0, l0, h1, l1;
                cvt_pair(ra[j].x, ra[j].y, h0, l0);
                cvt_pair(ra[j].z, ra[j].w, h1, l1);
                *(uint2*)(base + off)          = make_uint2(h0, h1);
                *(uint2*)(base + off + 10240)  = make_uint2(l0, l1);
                cvt_pair(rb[j].x, rb[j].y, h0, l0);
                cvt_pair(rb[j].z, rb[j].w, h1, l1);
                *(uint2*)(base + off + 20480)  = make_uint2(h0, h1);
                *(uint2*)(base + off + 30720)  = make_uint2(l0, l1);
            }
        }
        __syncthreads();
    }

    // epilogue
#pragma unroll
    for (int m = 0; m < 2; m++) {
        int r0 = bm + wm * 32 + m * 16 + (lane >> 2);
#pragma unroll
        for (int n = 0; n < 8; n++) {
            int c0 = bn + wn * 64 + n * 8 + (lane & 3) * 2;
            float* p0 = C + (size_t)r0 * N + c0;
            float* p1 = C + (size_t)(r0 + 8) * N + c0;
            float v0 = acc[m][n][0], v1 = acc[m][n][1];
            float v2 = acc[m][n][2], v3 = acc[m][n][3];
            if (MODE == 1) {
                float b0 = (c0 < N) ? bias[c0] : 0.f;
                float b1 = (c0 + 1 < N) ? bias[c0 + 1] : 0.f;
                v0 = fast_sigmoid(v0 + b0); v1 = fast_sigmoid(v1 + b1);
                v2 = fast_sigmoid(v2 + b0); v3 = fast_sigmoid(v3 + b1);
            }
            if (MODE == 2) {
                if (c0 < N)     { p0[0] += v0; p1[0] += v2; }
                if (c0 + 1 < N) { p0[1] += v1; p1[1] += v3; }
            } else {
                if (c0 < N)     { p0[0] = v0; p1[0] = v2; }
                if (c0 + 1 < N) { p0[1] = v1; p1[1] = v3; }
            }
        }
    }
}

// ---------------- driver -----------------------------------------------------
extern "C" void kernel_launch(void* const* d_in, const int* in_sizes, int n_in,
                              void* d_out, int out_size) {
    const int*   tokens = (const int*)  d_in[0];
    const float* emb    = (const float*)d_in[1];
    const float* ln_g   = (const float*)d_in[2];
    const float* ln_b   = (const float*)d_in[3];
    const float* in_w   = (const float*)d_in[4];
    const float* conv_w = (const float*)d_in[5];
    const float* conv_b = (const float*)d_in[6];
    const float* dt_w   = (const float*)d_in[7];
    const float* dt_b   = (const float*)d_in[8];
    const float* A_log  = (const float*)d_in[9];
    const float* D_par  = (const float*)d_in[10];
    const float* out_w  = (const float*)d_in[11];
    const float* lnf_g  = (const float*)d_in[12];
    const float* lnf_b  = (const float*)d_in[13];
    const float* head_w = (const float*)d_in[14];
    float* out = (float*)d_out;

    float *x, *xn, *xr, *xc, *dt, *y;
    cudaGetSymbolAddress((void**)&x,  g_x);
    cudaGetSymbolAddress((void**)&xn, g_xn);
    cudaGetSymbolAddress((void**)&xr, g_xr);
    cudaGetSymbolAddress((void**)&xc, g_xc);
    cudaGetSymbolAddress((void**)&dt, g_dt);
    cudaGetSymbolAddress((void**)&y,  g_y);

    cudaFuncSetAttribute(gemm_mma<0>, cudaFuncAttributeMaxDynamicSharedMemorySize, GEMM_SMEM);
    cudaFuncSetAttribute(gemm_mma<1>, cudaFuncAttributeMaxDynamicSharedMemorySize, GEMM_SMEM);
    cudaFuncSetAttribute(gemm_mma<2>, cudaFuncAttributeMaxDynamicSharedMemorySize, GEMM_SMEM);

    embed_kernel<<<BLD, 192>>>(tokens, emb);

    for (int l = 0; l < 4; l++) {
        ln_kernel<<<BLD, 256>>>(x, ln_g + l * DIM, ln_b + l * DIM, xn);
        // xr = xn @ in_w^T  (1024 x 1536)
        gemm_mma<0><<<dim3(8, 12), 256, GEMM_SMEM>>>(
            xn, in_w + (size_t)l * 2 * DIM * DIM, nullptr, xr, 2 * DIM, DIM);
        conv_silu_kernel<<<(BLD * DIM + 255) / 256, 256>>>(conv_w + l * DIM * 3,
                                                           conv_b + l * DIM);
        // dt = sigmoid(xc @ dt_w^T + dt_b)  (1024 x 768)
        gemm_mma<1><<<dim3(8, 6), 256, GEMM_SMEM>>>(
            xc, dt_w + (size_t)l * DIM * DIM, dt_b + l * DIM, dt, DIM, DIM);
        scan_kernel<<<96, 256>>>(A_log + l * DIM * NSTATE, D_par + l * DIM);
        // x += y @ out_w^T
        gemm_mma<2><<<dim3(8, 6), 256, GEMM_SMEM>>>(
            y, out_w + (size_t)l * DIM * DIM, nullptr, x, DIM, DIM);
    }

    ln_kernel<<<BLD, 256>>>(x, lnf_g, lnf_b, xn);
    // logits = xn @ head_w^T  (1024 x 50257)
    gemm_mma<0><<<dim3(8, (NVOC + 127) / 128), 256, GEMM_SMEM>>>(
        xn, head_w, nullptr, out, NVOC, DIM);
    (void)in_sizes; (void)n_in; (void)out_size;
}